// round 12
// baseline (speedup 1.0000x reference)
#include <cuda_runtime.h>
#include <cstdint>

#define NB 32
#define NT 1024
#define ND 512
#define NU 512
#define NR (NT / 2)   // rounds: 2 steps (chains) per round

// static scratch (no allocation): z = x@W + xshift@W2, plus W2=W@R, R2=R@R
__device__ float g_z[NB * NT * NU];     // 64MB
__device__ float g_W2[ND * NU];         // 1MB
__device__ float g_R2[NU * NU];         // 1MB

// ---------------- f32x2 packed helpers ----------------
__device__ __forceinline__ unsigned long long pk2(float x, float y) {
    unsigned long long r;
    asm("mov.b64 %0, {%1, %2};" : "=l"(r) : "f"(x), "f"(y));
    return r;
}
__device__ __forceinline__ unsigned long long pk2s(float x) {
    unsigned long long r;
    asm("mov.b64 %0, {%1, %1};" : "=l"(r) : "f"(x));
    return r;
}
__device__ __forceinline__ void fma2(unsigned long long& d, unsigned long long a,
                                     unsigned long long b) {
    asm("fma.rn.f32x2 %0, %1, %2, %0;" : "+l"(d) : "l"(a), "l"(b));
}
__device__ __forceinline__ float2 upk2(unsigned long long a) {
    float2 r;
    asm("mov.b64 {%0, %1}, %2;" : "=f"(r.x), "=f"(r.y) : "l"(a));
    return r;
}

// ======================================================================
// Kernel 0: W2 = W @ R (z=0), R2 = R @ R (z=1).  512x512x512 each.
// ======================================================================
__global__ __launch_bounds__(256) void prep_gemm(const float* __restrict__ W,
                                                 const float* __restrict__ Rm) {
    __shared__ float As[8][128];
    __shared__ float Bs[8][128];

    const float* A = (blockIdx.z == 0) ? W : Rm;
    const float* B = Rm;
    float* O = (blockIdx.z == 0) ? g_W2 : g_R2;

    const int tid = threadIdx.x;
    const int m0 = blockIdx.y * 128;
    const int n0 = blockIdx.x * 128;

    const int ar = tid >> 1;
    const int ac = (tid & 1) * 4;
    const int br = tid >> 5;
    const int bc = (tid & 31) * 4;
    const int tx = tid & 15;
    const int ty = tid >> 4;

    unsigned long long acc[8][4];
#pragma unroll
    for (int i = 0; i < 8; i++)
#pragma unroll
        for (int j = 0; j < 4; j++) acc[i][j] = 0ull;

    float4 xa = *reinterpret_cast<const float4*>(&A[(size_t)(m0 + ar) * ND + ac]);
    float4 wb = *reinterpret_cast<const float4*>(&B[(size_t)br * NU + n0 + bc]);

    const int KT = ND / 8;
    for (int kt = 0; kt < KT; kt++) {
        As[ac + 0][ar] = xa.x; As[ac + 1][ar] = xa.y;
        As[ac + 2][ar] = xa.z; As[ac + 3][ar] = xa.w;
        *reinterpret_cast<float4*>(&Bs[br][bc]) = wb;
        __syncthreads();
        if (kt + 1 < KT) {
            xa = *reinterpret_cast<const float4*>(&A[(size_t)(m0 + ar) * ND + (kt + 1) * 8 + ac]);
            wb = *reinterpret_cast<const float4*>(&B[(size_t)((kt + 1) * 8 + br) * NU + n0 + bc]);
        }
#pragma unroll
        for (int k = 0; k < 8; k++) {
            float4 a0 = *reinterpret_cast<const float4*>(&As[k][ty * 8]);
            float4 a1 = *reinterpret_cast<const float4*>(&As[k][ty * 8 + 4]);
            ulonglong2 bq0 = *reinterpret_cast<const ulonglong2*>(&Bs[k][tx * 8]);
            ulonglong2 bq1 = *reinterpret_cast<const ulonglong2*>(&Bs[k][tx * 8 + 4]);
            float av[8] = {a0.x, a0.y, a0.z, a0.w, a1.x, a1.y, a1.z, a1.w};
#pragma unroll
            for (int i = 0; i < 8; i++) {
                unsigned long long aa = pk2s(av[i]);
                fma2(acc[i][0], aa, bq0.x); fma2(acc[i][1], aa, bq0.y);
                fma2(acc[i][2], aa, bq1.x); fma2(acc[i][3], aa, bq1.y);
            }
        }
        __syncthreads();
    }
#pragma unroll
    for (int i = 0; i < 8; i++) {
        size_t row = (size_t)(m0 + ty * 8 + i);
        float2* op = reinterpret_cast<float2*>(&O[row * NU + n0 + tx * 8]);
        op[0] = upk2(acc[i][0]); op[1] = upk2(acc[i][1]);
        op[2] = upk2(acc[i][2]); op[3] = upk2(acc[i][3]);
    }
}

// ======================================================================
// Kernel 1: z = [x_t | x_{t-1}] @ [W ; W2]   (M=32768, K=1024)
// z_t = xw_t + xw_{t-1}@R ; rows with t==0 mask the second half to zero.
// ======================================================================
__device__ __forceinline__ float4 loadA_cat(const float* __restrict__ X, int m, int k) {
    if (k < ND) return *reinterpret_cast<const float4*>(&X[(size_t)m * ND + k]);
    if ((m & (NT - 1)) == 0) return make_float4(0.f, 0.f, 0.f, 0.f);
    return *reinterpret_cast<const float4*>(&X[(size_t)(m - 1) * ND + (k - ND)]);
}
__device__ __forceinline__ float4 loadB_cat(const float* __restrict__ W, int kk, int n) {
    if (kk < ND) return *reinterpret_cast<const float4*>(&W[(size_t)kk * NU + n]);
    return *reinterpret_cast<const float4*>(&g_W2[(size_t)(kk - ND) * NU + n]);
}

__global__ __launch_bounds__(256) void zcat_gemm(const float* __restrict__ X,
                                                 const float* __restrict__ W) {
    __shared__ float As[8][128];
    __shared__ float Bs[8][128];

    const int tid = threadIdx.x;
    const int m0 = blockIdx.y * 128;
    const int n0 = blockIdx.x * 128;

    const int ar = tid >> 1;
    const int ac = (tid & 1) * 4;
    const int br = tid >> 5;
    const int bc = (tid & 31) * 4;
    const int tx = tid & 15;
    const int ty = tid >> 4;

    unsigned long long acc[8][4];
#pragma unroll
    for (int i = 0; i < 8; i++)
#pragma unroll
        for (int j = 0; j < 4; j++) acc[i][j] = 0ull;

    float4 xa = loadA_cat(X, m0 + ar, ac);
    float4 wb = loadB_cat(W, br, n0 + bc);

    const int KT = (2 * ND) / 8;  // 128
    for (int kt = 0; kt < KT; kt++) {
        As[ac + 0][ar] = xa.x; As[ac + 1][ar] = xa.y;
        As[ac + 2][ar] = xa.z; As[ac + 3][ar] = xa.w;
        *reinterpret_cast<float4*>(&Bs[br][bc]) = wb;
        __syncthreads();
        if (kt + 1 < KT) {
            xa = loadA_cat(X, m0 + ar, (kt + 1) * 8 + ac);
            wb = loadB_cat(W, (kt + 1) * 8 + br, n0 + bc);
        }
#pragma unroll
        for (int k = 0; k < 8; k++) {
            float4 a0 = *reinterpret_cast<const float4*>(&As[k][ty * 8]);
            float4 a1 = *reinterpret_cast<const float4*>(&As[k][ty * 8 + 4]);
            ulonglong2 bq0 = *reinterpret_cast<const ulonglong2*>(&Bs[k][tx * 8]);
            ulonglong2 bq1 = *reinterpret_cast<const ulonglong2*>(&Bs[k][tx * 8 + 4]);
            float av[8] = {a0.x, a0.y, a0.z, a0.w, a1.x, a1.y, a1.z, a1.w};
#pragma unroll
            for (int i = 0; i < 8; i++) {
                unsigned long long aa = pk2s(av[i]);
                fma2(acc[i][0], aa, bq0.x); fma2(acc[i][1], aa, bq0.y);
                fma2(acc[i][2], aa, bq1.x); fma2(acc[i][3], aa, bq1.y);
            }
        }
        __syncthreads();
    }
#pragma unroll
    for (int i = 0; i < 8; i++) {
        size_t row = (size_t)(m0 + ty * 8 + i);
        float2* op = reinterpret_cast<float2*>(&g_z[row * NU + n0 + tx * 8]);
        op[0] = upk2(acc[i][0]); op[1] = upk2(acc[i][1]);
        op[2] = upk2(acc[i][2]); op[3] = upk2(acc[i][3]);
    }
}

// ======================================================================
// Kernel 2: lag-2 scan, batched rounds, 512 THREADS (4 warps/SMSP):
// the matvec section is latency-bound at 256 threads (R11 decomposition:
// scaffolding only ~530 cyc/round, compute ~4500 vs 1024 issue floor),
// so double the warps and halve per-thread work. Reduction buffer is
// single-chain (48KB static smem cap) and reused across the two chains.
// ======================================================================
__global__ __launch_bounds__(512, 1) __cluster_dims__(8, 1, 1)
void scan_kernel(float* __restrict__ out) {
    __shared__ alignas(16) float hbuf[2][8][2][2][64];  // [par][srcRank][chain][batch][unit] 16KB
    __shared__ alignas(16) float red[32][2][16][4];     // [kb][b][q][j]  16KB (per chain, reused)
    __shared__ alignas(8) unsigned long long mbar[2];   // [parity]

    const int tid = threadIdx.x;
    uint32_t rank;
    asm("mov.u32 %0, %%cluster_ctarank;" : "=r"(rank));
    const int cluster = blockIdx.x >> 3;
    const int b0 = cluster * 2;
    const int useg = (int)rank * 64;

    const int q = tid & 15;                   // u-quad (16 quads = 64 units)
    const int kb = tid >> 4;                  // k block 0..31 (32 blocks of 16)
    const int ug = useg + q * 4;
    const int k0 = kb * 16;

    // R2 slice as k-pairs: Rp[j][i] = {R2[k0+2i][ug+j], R2[k0+2i+1][ug+j]}
    unsigned long long Rp[4][8];
#pragma unroll
    for (int i = 0; i < 8; i++) {
        float4 v0 = *reinterpret_cast<const float4*>(&g_R2[(size_t)(k0 + 2 * i) * NU + ug]);
        float4 v1 = *reinterpret_cast<const float4*>(&g_R2[(size_t)(k0 + 2 * i + 1) * NU + ug]);
        Rp[0][i] = pk2(v0.x, v1.x);
        Rp[1][i] = pk2(v0.y, v1.y);
        Rp[2][i] = pk2(v0.z, v1.z);
        Rp[3][i] = pk2(v0.w, v1.w);
    }

    // zero both h parities (round 0 reads parity 0 = zeros -> h = z)
    for (int i = tid; i < 2 * 8 * 2 * 2 * 64; i += 512) (&hbuf[0][0][0][0][0])[i] = 0.f;

    uint32_t barL[2];
#pragma unroll
    for (int p = 0; p < 2; p++)
        barL[p] = (uint32_t)__cvta_generic_to_shared(&mbar[p]);
    if (tid == 0) {
#pragma unroll
        for (int p = 0; p < 2; p++) {
            asm volatile("mbarrier.init.shared.b64 [%0], 1;" :: "r"(barL[p]) : "memory");
            asm volatile("mbarrier.arrive.expect_tx.shared.b64 _, [%0], %1;"
                         :: "r"(barL[p]), "r"(7168) : "memory");  // 7 x 1024B
        }
    }
    __syncthreads();
    // one-time rendezvous: inits/arms + zeroed hbuf visible before any bulk
    asm volatile("barrier.cluster.arrive.aligned;" ::: "memory");
    asm volatile("barrier.cluster.wait.aligned;" ::: "memory");

    // owner threads (tid<128): one (batch, unit) output each, both chains
    const bool owner = tid < 128;
    const int ob = tid >> 6;
    const int ou = tid & 63;
    const int oq = ou >> 2, oj = ou & 3;
    const float* zbase = &g_z[((size_t)(b0 + ob) * NT) * NU + useg + ou];
    float* obase = &out[((size_t)(b0 + ob) * NT) * NU + useg + ou];
    float zcur[2];
    zcur[0] = owner ? zbase[0] : 0.f;              // t = 0
    zcur[1] = owner ? zbase[(size_t)NU] : 0.f;     // t = 1

    // sender endpoint tables (tid 0..6, one dest CTA each), per write-parity
    uint32_t srcA[2], dstA[2], mbR[2];
    if (tid < 7) {
        const int d = (tid < (int)rank) ? tid : tid + 1;
#pragma unroll
        for (int wp = 0; wp < 2; wp++) {
            srcA[wp] = (uint32_t)__cvta_generic_to_shared(&hbuf[wp][rank][0][0][0]);
            asm("mapa.shared::cluster.u32 %0, %1, %2;"
                : "=r"(dstA[wp]) : "r"(srcA[wp]), "r"(d));
            asm("mapa.shared::cluster.u32 %0, %1, %2;"
                : "=r"(mbR[wp]) : "r"(barL[wp]), "r"(d));
        }
    }

    int par2[2] = {0, 0};

    for (int r = 0; r < NR; r++) {
        const int p = r & 1;          // read parity
        const int wp = p ^ 1;         // write parity (consumed at round r+1)

        if (r >= 1) {
            const uint32_t ba = barL[p];
            const uint32_t ph = (uint32_t)par2[p];
            uint32_t done;
            asm volatile(
                "{\n\t.reg .pred p;\n\t"
                "mbarrier.try_wait.parity.acquire.cta.shared::cta.b64 p, [%1], %2;\n\t"
                "selp.b32 %0, 1, 0, p;\n\t}"
                : "=r"(done) : "r"(ba), "r"(ph) : "memory");
            while (!done) {
                asm volatile(
                    "{\n\t.reg .pred p;\n\t"
                    "mbarrier.try_wait.parity.acquire.cta.shared::cta.b64 p, [%1], %2, 0x989680;\n\t"
                    "selp.b32 %0, 1, 0, p;\n\t}"
                    : "=r"(done) : "r"(ba), "r"(ph) : "memory");
            }
            par2[p] ^= 1;
            // re-arm for round r+2 (tid0's own sends at r follow in program
            // order -> peers' r+1 sends are gated by my r sends -> causal)
            if (tid == 0 && (r + 2) < NR) {
                asm volatile("mbarrier.arrive.expect_tx.shared.b64 _, [%0], %1;"
                             :: "r"(ba), "r"(7168) : "memory");
            }
        }
        // sync0: orders prev round's local staging stores + red reuse
        __syncthreads();

        // prefetch z for round r+1 (consumed next round -> full round to land)
        float znxt[2] = {0.f, 0.f};
        if (owner && (r + 1) < NR) {
            znxt[0] = zbase[(size_t)(2 * (r + 1) + 0) * NU];
            znxt[1] = zbase[(size_t)(2 * (r + 1) + 1) * NU];
        }

        // ---- chain 0 matvec (16 k per thread) + stage into red ----
        unsigned long long acc[2][4][2];
        {
            const float* h0 = &hbuf[p][kb >> 2][0][0][(kb & 3) * 16];
            const float* h1 = &hbuf[p][kb >> 2][0][1][(kb & 3) * 16];
#pragma unroll
            for (int b = 0; b < 2; b++)
#pragma unroll
                for (int j = 0; j < 4; j++) { acc[b][j][0] = 0ull; acc[b][j][1] = 0ull; }
#pragma unroll
            for (int g = 0; g < 4; g++) {
                ulonglong2 hp0 = *reinterpret_cast<const ulonglong2*>(&h0[g * 4]);
                ulonglong2 hp1 = *reinterpret_cast<const ulonglong2*>(&h1[g * 4]);
#pragma unroll
                for (int j = 0; j < 4; j++) {
                    fma2(acc[0][j][0], Rp[j][2 * g + 0], hp0.x);
                    fma2(acc[0][j][1], Rp[j][2 * g + 1], hp0.y);
                    fma2(acc[1][j][0], Rp[j][2 * g + 0], hp1.x);
                    fma2(acc[1][j][1], Rp[j][2 * g + 1], hp1.y);
                }
            }
#pragma unroll
            for (int b = 0; b < 2; b++) {
                float pj[4];
#pragma unroll
                for (int j = 0; j < 4; j++) {
                    float2 s0 = upk2(acc[b][j][0]);
                    float2 s1 = upk2(acc[b][j][1]);
                    pj[j] = (s0.x + s0.y) + (s1.x + s1.y);
                }
                *reinterpret_cast<float4*>(&red[kb][b][q][0]) =
                    make_float4(pj[0], pj[1], pj[2], pj[3]);
            }
        }

        // ---- chain 1 matvec (acc reused), partials kept in registers ----
        float pj1[2][4];
        {
            const float* h0 = &hbuf[p][kb >> 2][1][0][(kb & 3) * 16];
            const float* h1 = &hbuf[p][kb >> 2][1][1][(kb & 3) * 16];
#pragma unroll
            for (int b = 0; b < 2; b++)
#pragma unroll
                for (int j = 0; j < 4; j++) { acc[b][j][0] = 0ull; acc[b][j][1] = 0ull; }
#pragma unroll
            for (int g = 0; g < 4; g++) {
                ulonglong2 hp0 = *reinterpret_cast<const ulonglong2*>(&h0[g * 4]);
                ulonglong2 hp1 = *reinterpret_cast<const ulonglong2*>(&h1[g * 4]);
#pragma unroll
                for (int j = 0; j < 4; j++) {
                    fma2(acc[0][j][0], Rp[j][2 * g + 0], hp0.x);
                    fma2(acc[0][j][1], Rp[j][2 * g + 1], hp0.y);
                    fma2(acc[1][j][0], Rp[j][2 * g + 0], hp1.x);
                    fma2(acc[1][j][1], Rp[j][2 * g + 1], hp1.y);
                }
            }
#pragma unroll
            for (int b = 0; b < 2; b++)
#pragma unroll
                for (int j = 0; j < 4; j++) {
                    float2 s0 = upk2(acc[b][j][0]);
                    float2 s1 = upk2(acc[b][j][1]);
                    pj1[b][j] = (s0.x + s0.y) + (s1.x + s1.y);
                }
        }
        __syncthreads();   // sync1: chain-0 partials staged (hbuf[p] reads done)

        float val0 = 0.f;
        if (owner) {
            float s = 0.f;
#pragma unroll
            for (int r32 = 0; r32 < 32; r32++) s += red[r32][ob][oq][oj];
            val0 = zcur[0] + s;
        }
        __syncthreads();   // sync2: owners done reading red (chain 0)

        // stage chain-1 partials
#pragma unroll
        for (int b = 0; b < 2; b++)
            *reinterpret_cast<float4*>(&red[kb][b][q][0]) =
                make_float4(pj1[b][0], pj1[b][1], pj1[b][2], pj1[b][3]);
        __syncthreads();   // sync3: chain-1 partials staged

        if (owner) {
            float s = 0.f;
#pragma unroll
            for (int r32 = 0; r32 < 32; r32++) s += red[r32][ob][oq][oj];
            const float val1 = zcur[1] + s;
            obase[(size_t)(2 * r + 0) * NU] = val0;
            obase[(size_t)(2 * r + 1) * NU] = val1;

            if (r + 1 < NR) {
                hbuf[wp][rank][0][ob][ou] = val0;   // local staging (own slice)
                hbuf[wp][rank][1][ob][ou] = val1;
                asm volatile("bar.sync 1, 128;" ::: "memory");  // slice complete
                if (tid < 7) {
                    asm volatile("fence.proxy.async.shared::cta;" ::: "memory");
                    asm volatile(
                        "cp.async.bulk.shared::cluster.shared::cta.mbarrier::complete_tx::bytes "
                        "[%0], [%1], %2, [%3];"
                        :: "r"(dstA[wp]), "r"(srcA[wp]), "r"(1024), "r"(mbR[wp])
                        : "memory");
                }
            }
        }
        zcur[0] = znxt[0];
        zcur[1] = znxt[1];
    }

    // final rendezvous: no CTA exits while peers could still touch its smem
    asm volatile("barrier.cluster.arrive.aligned;" ::: "memory");
    asm volatile("barrier.cluster.wait.aligned;" ::: "memory");
}

// ======================================================================
extern "C" void kernel_launch(void* const* d_in, const int* in_sizes, int n_in,
                              void* d_out, int out_size) {
    const float* x = (const float*)d_in[0];            // [32,1024,512]
    const float* W = (const float*)d_in[1];            // kernel [512,512]
    const float* R = (const float*)d_in[2];            // recurrent_kernel [512,512]
    float* out = (float*)d_out;                        // [32,1024,512]

    prep_gemm<<<dim3(4, 4, 2), 256>>>(W, R);           // W2 = W@R, R2 = R@R
    dim3 gg(NU / 128, (NB * NT) / 128);                // (4, 256)
    zcat_gemm<<<gg, 256>>>(x, W);                      // z = x@W + xshift@W2
    scan_kernel<<<128, 512>>>(out);                    // 512-thread lag-2 scan
}

// round 13
// speedup vs baseline: 1.7999x; 1.7999x over previous
#include <cuda_runtime.h>
#include <cstdint>

#define NB 32
#define NT 1024
#define ND 512
#define NU 512
#define NR (NT / 2)   // rounds: 2 steps (chains) per round

// static scratch (no allocation): z = x@W + xshift@W2, plus W2=W@R, R2=R@R
__device__ float g_z[NB * NT * NU];     // 64MB
__device__ float g_W2[ND * NU];         // 1MB
__device__ float g_R2[NU * NU];         // 1MB

// ---------------- f32x2 packed helpers ----------------
__device__ __forceinline__ unsigned long long pk2(float x, float y) {
    unsigned long long r;
    asm("mov.b64 %0, {%1, %2};" : "=l"(r) : "f"(x), "f"(y));
    return r;
}
__device__ __forceinline__ unsigned long long pk2s(float x) {
    unsigned long long r;
    asm("mov.b64 %0, {%1, %1};" : "=l"(r) : "f"(x));
    return r;
}
__device__ __forceinline__ void fma2(unsigned long long& d, unsigned long long a,
                                     unsigned long long b) {
    asm("fma.rn.f32x2 %0, %1, %2, %0;" : "+l"(d) : "l"(a), "l"(b));
}
__device__ __forceinline__ float2 upk2(unsigned long long a) {
    float2 r;
    asm("mov.b64 {%0, %1}, %2;" : "=f"(r.x), "=f"(r.y) : "l"(a));
    return r;
}

// ======================================================================
// Kernel 0: W2 = W @ R (z=0), R2 = R @ R (z=1).  512x512x512 each.
// ======================================================================
__global__ __launch_bounds__(256) void prep_gemm(const float* __restrict__ W,
                                                 const float* __restrict__ Rm) {
    __shared__ float As[8][128];
    __shared__ float Bs[8][128];

    const float* A = (blockIdx.z == 0) ? W : Rm;
    const float* B = Rm;
    float* O = (blockIdx.z == 0) ? g_W2 : g_R2;

    const int tid = threadIdx.x;
    const int m0 = blockIdx.y * 128;
    const int n0 = blockIdx.x * 128;

    const int ar = tid >> 1;
    const int ac = (tid & 1) * 4;
    const int br = tid >> 5;
    const int bc = (tid & 31) * 4;
    const int tx = tid & 15;
    const int ty = tid >> 4;

    unsigned long long acc[8][4];
#pragma unroll
    for (int i = 0; i < 8; i++)
#pragma unroll
        for (int j = 0; j < 4; j++) acc[i][j] = 0ull;

    float4 xa = *reinterpret_cast<const float4*>(&A[(size_t)(m0 + ar) * ND + ac]);
    float4 wb = *reinterpret_cast<const float4*>(&B[(size_t)br * NU + n0 + bc]);

    const int KT = ND / 8;
    for (int kt = 0; kt < KT; kt++) {
        As[ac + 0][ar] = xa.x; As[ac + 1][ar] = xa.y;
        As[ac + 2][ar] = xa.z; As[ac + 3][ar] = xa.w;
        *reinterpret_cast<float4*>(&Bs[br][bc]) = wb;
        __syncthreads();
        if (kt + 1 < KT) {
            xa = *reinterpret_cast<const float4*>(&A[(size_t)(m0 + ar) * ND + (kt + 1) * 8 + ac]);
            wb = *reinterpret_cast<const float4*>(&B[(size_t)((kt + 1) * 8 + br) * NU + n0 + bc]);
        }
#pragma unroll
        for (int k = 0; k < 8; k++) {
            float4 a0 = *reinterpret_cast<const float4*>(&As[k][ty * 8]);
            float4 a1 = *reinterpret_cast<const float4*>(&As[k][ty * 8 + 4]);
            ulonglong2 bq0 = *reinterpret_cast<const ulonglong2*>(&Bs[k][tx * 8]);
            ulonglong2 bq1 = *reinterpret_cast<const ulonglong2*>(&Bs[k][tx * 8 + 4]);
            float av[8] = {a0.x, a0.y, a0.z, a0.w, a1.x, a1.y, a1.z, a1.w};
#pragma unroll
            for (int i = 0; i < 8; i++) {
                unsigned long long aa = pk2s(av[i]);
                fma2(acc[i][0], aa, bq0.x); fma2(acc[i][1], aa, bq0.y);
                fma2(acc[i][2], aa, bq1.x); fma2(acc[i][3], aa, bq1.y);
            }
        }
        __syncthreads();
    }
#pragma unroll
    for (int i = 0; i < 8; i++) {
        size_t row = (size_t)(m0 + ty * 8 + i);
        float2* op = reinterpret_cast<float2*>(&O[row * NU + n0 + tx * 8]);
        op[0] = upk2(acc[i][0]); op[1] = upk2(acc[i][1]);
        op[2] = upk2(acc[i][2]); op[3] = upk2(acc[i][3]);
    }
}

// ======================================================================
// Kernel 1: z = [x_t | x_{t-1}] @ [W ; W2]   (M=32768, K=1024)
// DOUBLE-BUFFERED smem pipeline: ONE __syncthreads per K-tile (was two),
// LDG for tile k+1 issued before compute of tile k, stores to the idle
// stage after compute. __launch_bounds__(256,2) pins 2 blocks/SM.
// ======================================================================
__device__ __forceinline__ float4 loadA_cat(const float* __restrict__ X, int m, int k) {
    if (k < ND) return *reinterpret_cast<const float4*>(&X[(size_t)m * ND + k]);
    if ((m & (NT - 1)) == 0) return make_float4(0.f, 0.f, 0.f, 0.f);
    return *reinterpret_cast<const float4*>(&X[(size_t)(m - 1) * ND + (k - ND)]);
}
__device__ __forceinline__ float4 loadB_cat(const float* __restrict__ W, int kk, int n) {
    if (kk < ND) return *reinterpret_cast<const float4*>(&W[(size_t)kk * NU + n]);
    return *reinterpret_cast<const float4*>(&g_W2[(size_t)(kk - ND) * NU + n]);
}

__global__ __launch_bounds__(256, 2) void zcat_gemm(const float* __restrict__ X,
                                                    const float* __restrict__ W) {
    __shared__ float As[2][8][128];
    __shared__ float Bs[2][8][128];

    const int tid = threadIdx.x;
    const int m0 = blockIdx.y * 128;
    const int n0 = blockIdx.x * 128;

    const int ar = tid >> 1;
    const int ac = (tid & 1) * 4;
    const int br = tid >> 5;
    const int bc = (tid & 31) * 4;
    const int tx = tid & 15;
    const int ty = tid >> 4;

    unsigned long long acc[8][4];
#pragma unroll
    for (int i = 0; i < 8; i++)
#pragma unroll
        for (int j = 0; j < 4; j++) acc[i][j] = 0ull;

    // stage 0 fill
    {
        float4 xa = loadA_cat(X, m0 + ar, ac);
        float4 wb = loadB_cat(W, br, n0 + bc);
        As[0][ac + 0][ar] = xa.x; As[0][ac + 1][ar] = xa.y;
        As[0][ac + 2][ar] = xa.z; As[0][ac + 3][ar] = xa.w;
        *reinterpret_cast<float4*>(&Bs[0][br][bc]) = wb;
    }
    __syncthreads();

    const int KT = (2 * ND) / 8;  // 128
    for (int kt = 0; kt < KT; kt++) {
        const int cur = kt & 1, nxt = cur ^ 1;

        // prefetch tile kt+1 from gmem (overlaps compute below)
        float4 xa, wb;
        const bool more = (kt + 1) < KT;
        if (more) {
            xa = loadA_cat(X, m0 + ar, (kt + 1) * 8 + ac);
            wb = loadB_cat(W, (kt + 1) * 8 + br, n0 + bc);
        }

        // compute on stage cur
#pragma unroll
        for (int k = 0; k < 8; k++) {
            float4 a0 = *reinterpret_cast<const float4*>(&As[cur][k][ty * 8]);
            float4 a1 = *reinterpret_cast<const float4*>(&As[cur][k][ty * 8 + 4]);
            ulonglong2 bq0 = *reinterpret_cast<const ulonglong2*>(&Bs[cur][k][tx * 8]);
            ulonglong2 bq1 = *reinterpret_cast<const ulonglong2*>(&Bs[cur][k][tx * 8 + 4]);
            float av[8] = {a0.x, a0.y, a0.z, a0.w, a1.x, a1.y, a1.z, a1.w};
#pragma unroll
            for (int i = 0; i < 8; i++) {
                unsigned long long aa = pk2s(av[i]);
                fma2(acc[i][0], aa, bq0.x); fma2(acc[i][1], aa, bq0.y);
                fma2(acc[i][2], aa, bq1.x); fma2(acc[i][3], aa, bq1.y);
            }
        }

        // store prefetched tile into the idle stage
        if (more) {
            As[nxt][ac + 0][ar] = xa.x; As[nxt][ac + 1][ar] = xa.y;
            As[nxt][ac + 2][ar] = xa.z; As[nxt][ac + 3][ar] = xa.w;
            *reinterpret_cast<float4*>(&Bs[nxt][br][bc]) = wb;
        }
        __syncthreads();   // single barrier per tile
    }

#pragma unroll
    for (int i = 0; i < 8; i++) {
        size_t row = (size_t)(m0 + ty * 8 + i);
        float2* op = reinterpret_cast<float2*>(&g_z[row * NU + n0 + tx * 8]);
        op[0] = upk2(acc[i][0]); op[1] = upk2(acc[i][1]);
        op[2] = upk2(acc[i][2]); op[3] = upk2(acc[i][3]);
    }
}

// ======================================================================
// Kernel 2: lag-2 scan, batched rounds (EXACT R11 config — best known:
// 256 threads, register-resident R2, merged 2-chain rounds, dual-parity
// mbarriers, cta-scope acquire, 7x1KB aggregated DSMEM bulks).
// ======================================================================
__global__ __launch_bounds__(256, 1) __cluster_dims__(8, 1, 1)
void scan_kernel(float* __restrict__ out) {
    __shared__ alignas(16) float hbuf[2][8][2][2][64];  // [par][srcRank][chain][batch][unit] 16KB
    __shared__ alignas(16) float red[2][16][2][16][4];  // [chain][kb][b][q][j]               16KB
    __shared__ alignas(8) unsigned long long mbar[2];   // [parity]

    const int tid = threadIdx.x;
    uint32_t rank;
    asm("mov.u32 %0, %%cluster_ctarank;" : "=r"(rank));
    const int cluster = blockIdx.x >> 3;
    const int b0 = cluster * 2;
    const int useg = (int)rank * 64;

    const int q = tid & 15;                   // u-quad (16 quads = 64 units)
    const int kb = tid >> 4;                  // k block (16 blocks of 32)
    const int ug = useg + q * 4;
    const int k0 = kb * 32;

    // R2 slice as k-pairs: Rp[j][i] = {R2[k0+2i][ug+j], R2[k0+2i+1][ug+j]}
    unsigned long long Rp[4][16];
#pragma unroll
    for (int i = 0; i < 16; i++) {
        float4 v0 = *reinterpret_cast<const float4*>(&g_R2[(size_t)(k0 + 2 * i) * NU + ug]);
        float4 v1 = *reinterpret_cast<const float4*>(&g_R2[(size_t)(k0 + 2 * i + 1) * NU + ug]);
        Rp[0][i] = pk2(v0.x, v1.x);
        Rp[1][i] = pk2(v0.y, v1.y);
        Rp[2][i] = pk2(v0.z, v1.z);
        Rp[3][i] = pk2(v0.w, v1.w);
    }

    // zero both h parities (round 0 reads parity 0 = zeros -> h = z)
    for (int i = tid; i < 2 * 8 * 2 * 2 * 64; i += 256) (&hbuf[0][0][0][0][0])[i] = 0.f;

    uint32_t barL[2];
#pragma unroll
    for (int p = 0; p < 2; p++)
        barL[p] = (uint32_t)__cvta_generic_to_shared(&mbar[p]);
    if (tid == 0) {
#pragma unroll
        for (int p = 0; p < 2; p++) {
            asm volatile("mbarrier.init.shared.b64 [%0], 1;" :: "r"(barL[p]) : "memory");
            asm volatile("mbarrier.arrive.expect_tx.shared.b64 _, [%0], %1;"
                         :: "r"(barL[p]), "r"(7168) : "memory");  // 7 x 1024B
        }
    }
    __syncthreads();
    // one-time rendezvous: inits/arms + zeroed hbuf visible before any bulk
    asm volatile("barrier.cluster.arrive.aligned;" ::: "memory");
    asm volatile("barrier.cluster.wait.aligned;" ::: "memory");

    // owner threads (tid<128): one (batch, unit) output each, both chains
    const bool owner = tid < 128;
    const int ob = tid >> 6;
    const int ou = tid & 63;
    const int oq = ou >> 2, oj = ou & 3;
    const float* zbase = &g_z[((size_t)(b0 + ob) * NT) * NU + useg + ou];
    float* obase = &out[((size_t)(b0 + ob) * NT) * NU + useg + ou];
    float zcur[2];
    zcur[0] = owner ? zbase[0] : 0.f;              // t = 0
    zcur[1] = owner ? zbase[(size_t)NU] : 0.f;     // t = 1

    // sender endpoint tables (tid 0..6, one dest CTA each), per write-parity
    uint32_t srcA[2], dstA[2], mbR[2];
    if (tid < 7) {
        const int d = (tid < (int)rank) ? tid : tid + 1;
#pragma unroll
        for (int wp = 0; wp < 2; wp++) {
            srcA[wp] = (uint32_t)__cvta_generic_to_shared(&hbuf[wp][rank][0][0][0]);
            asm("mapa.shared::cluster.u32 %0, %1, %2;"
                : "=r"(dstA[wp]) : "r"(srcA[wp]), "r"(d));
            asm("mapa.shared::cluster.u32 %0, %1, %2;"
                : "=r"(mbR[wp]) : "r"(barL[wp]), "r"(d));
        }
    }

    int par2[2] = {0, 0};

    for (int r = 0; r < NR; r++) {
        const int p = r & 1;          // read parity
        const int wp = p ^ 1;         // write parity (consumed at round r+1)

        if (r >= 1) {
            const uint32_t ba = barL[p];
            const uint32_t ph = (uint32_t)par2[p];
            uint32_t done;
            asm volatile(
                "{\n\t.reg .pred p;\n\t"
                "mbarrier.try_wait.parity.acquire.cta.shared::cta.b64 p, [%1], %2;\n\t"
                "selp.b32 %0, 1, 0, p;\n\t}"
                : "=r"(done) : "r"(ba), "r"(ph) : "memory");
            while (!done) {
                asm volatile(
                    "{\n\t.reg .pred p;\n\t"
                    "mbarrier.try_wait.parity.acquire.cta.shared::cta.b64 p, [%1], %2, 0x989680;\n\t"
                    "selp.b32 %0, 1, 0, p;\n\t}"
                    : "=r"(done) : "r"(ba), "r"(ph) : "memory");
            }
            par2[p] ^= 1;
            // re-arm for round r+2 (tid0's own sends at r follow in program
            // order -> peers' r+1 sends are gated by my r sends -> causal)
            if (tid == 0 && (r + 2) < NR) {
                asm volatile("mbarrier.arrive.expect_tx.shared.b64 _, [%0], %1;"
                             :: "r"(ba), "r"(7168) : "memory");
            }
        }
        // ONE barrier per round: orders owners' round-(r-1) LOCAL staging
        // stores before all warps' reads this round (bulk arrivals are
        // ordered by the mbarrier; local stores need this).
        __syncthreads();

        // prefetch z for round r+1 (consumed next round -> full round to land)
        float znxt[2] = {0.f, 0.f};
        if (owner && (r + 1) < NR) {
            znxt[0] = zbase[(size_t)(2 * (r + 1) + 0) * NU];
            znxt[1] = zbase[(size_t)(2 * (r + 1) + 1) * NU];
        }

        // ---- matvec both chains, accumulators reused (reg pressure flat) ----
#pragma unroll
        for (int c = 0; c < 2; c++) {
            const float* h0 = &hbuf[p][kb >> 1][c][0][(kb & 1) * 32];
            const float* h1 = &hbuf[p][kb >> 1][c][1][(kb & 1) * 32];
            unsigned long long acc[2][4][2];
#pragma unroll
            for (int b = 0; b < 2; b++)
#pragma unroll
                for (int j = 0; j < 4; j++) { acc[b][j][0] = 0ull; acc[b][j][1] = 0ull; }

#pragma unroll
            for (int g = 0; g < 8; g++) {
                ulonglong2 hp0 = *reinterpret_cast<const ulonglong2*>(&h0[g * 4]);
                ulonglong2 hp1 = *reinterpret_cast<const ulonglong2*>(&h1[g * 4]);
#pragma unroll
                for (int j = 0; j < 4; j++) {
                    fma2(acc[0][j][0], Rp[j][2 * g + 0], hp0.x);
                    fma2(acc[0][j][1], Rp[j][2 * g + 1], hp0.y);
                    fma2(acc[1][j][0], Rp[j][2 * g + 0], hp1.x);
                    fma2(acc[1][j][1], Rp[j][2 * g + 1], hp1.y);
                }
            }
            // stash partials: one STS.128 per batch
#pragma unroll
            for (int b = 0; b < 2; b++) {
                float pj[4];
#pragma unroll
                for (int j = 0; j < 4; j++) {
                    float2 s0 = upk2(acc[b][j][0]);
                    float2 s1 = upk2(acc[b][j][1]);
                    pj[j] = (s0.x + s0.y) + (s1.x + s1.y);
                }
                *reinterpret_cast<float4*>(&red[c][kb][b][q][0]) =
                    make_float4(pj[0], pj[1], pj[2], pj[3]);
            }
        }
        __syncthreads();   // all partials staged (all 256 threads)

        if (owner) {
            float val[2];
#pragma unroll
            for (int c = 0; c < 2; c++) {
                float s = 0.f;
#pragma unroll
                for (int r8 = 0; r8 < 16; r8++) s += red[c][r8][ob][oq][oj];
                val[c] = zcur[c] + s;
                obase[(size_t)(2 * r + c) * NU] = val[c];
            }
            if (r + 1 < NR) {
                hbuf[wp][rank][0][ob][ou] = val[0];   // local staging (own slice)
                hbuf[wp][rank][1][ob][ou] = val[1];
                asm volatile("bar.sync 1, 128;" ::: "memory");  // slice complete
                if (tid < 7) {
                    asm volatile("fence.proxy.async.shared::cta;" ::: "memory");
                    asm volatile(
                        "cp.async.bulk.shared::cluster.shared::cta.mbarrier::complete_tx::bytes "
                        "[%0], [%1], %2, [%3];"
                        :: "r"(dstA[wp]), "r"(srcA[wp]), "r"(1024), "r"(mbR[wp])
                        : "memory");
                }
            }
        }
        zcur[0] = znxt[0];
        zcur[1] = znxt[1];
    }

    // final rendezvous: no CTA exits while peers could still touch its smem
    asm volatile("barrier.cluster.arrive.aligned;" ::: "memory");
    asm volatile("barrier.cluster.wait.aligned;" ::: "memory");
}

// ======================================================================
extern "C" void kernel_launch(void* const* d_in, const int* in_sizes, int n_in,
                              void* d_out, int out_size) {
    const float* x = (const float*)d_in[0];            // [32,1024,512]
    const float* W = (const float*)d_in[1];            // kernel [512,512]
    const float* R = (const float*)d_in[2];            // recurrent_kernel [512,512]
    float* out = (float*)d_out;                        // [32,1024,512]

    prep_gemm<<<dim3(4, 4, 2), 256>>>(W, R);           // W2 = W@R, R2 = R@R
    dim3 gg(NU / 128, (NB * NT) / 128);                // (4, 256)
    zcat_gemm<<<gg, 256>>>(x, W);                      // double-buffered z GEMM
    scan_kernel<<<128, 256>>>(out);                    // R11 lag-2 scan (best known)
}

// round 16
// speedup vs baseline: 2.0883x; 1.1602x over previous
#include <cuda_runtime.h>
#include <cuda_bf16.h>
#include <cstdint>

#define NB 32
#define NT 1024
#define ND 512
#define NU 512
#define NR (NT / 2)   // rounds: 2 steps (chains) per round
#define KCAT 1024     // concatenated K for z GEMM

// static scratch (no allocation)
__device__ float g_z[NB * NT * NU];                       // 64MB
__device__ float g_W2[ND * NU];                           // 1MB
__device__ float g_R2[NU * NU];                           // 1MB
__device__ __align__(16) __nv_bfloat16 g_Ahi[NB * NT * KCAT];  // 64MB
__device__ __align__(16) __nv_bfloat16 g_Alo[NB * NT * KCAT];  // 64MB
__device__ __align__(16) __nv_bfloat16 g_Wthi[NU * KCAT];      // 1MB  [n][k]
__device__ __align__(16) __nv_bfloat16 g_Wtlo[NU * KCAT];      // 1MB

// ---------------- f32x2 packed helpers ----------------
__device__ __forceinline__ unsigned long long pk2(float x, float y) {
    unsigned long long r;
    asm("mov.b64 %0, {%1, %2};" : "=l"(r) : "f"(x), "f"(y));
    return r;
}
__device__ __forceinline__ unsigned long long pk2s(float x) {
    unsigned long long r;
    asm("mov.b64 %0, {%1, %1};" : "=l"(r) : "f"(x));
    return r;
}
__device__ __forceinline__ void fma2(unsigned long long& d, unsigned long long a,
                                     unsigned long long b) {
    asm("fma.rn.f32x2 %0, %1, %2, %0;" : "+l"(d) : "l"(a), "l"(b));
}
__device__ __forceinline__ float2 upk2(unsigned long long a) {
    float2 r;
    asm("mov.b64 {%0, %1}, %2;" : "=f"(r.x), "=f"(r.y) : "l"(a));
    return r;
}
#define SWZ128(off) ((off) ^ (((off) >> 3) & 0x70))

// ======================================================================
// Kernel 0: W2 = W @ R (z=0), R2 = R @ R (z=1).  512x512x512 each.
// ======================================================================
__global__ __launch_bounds__(256) void prep_gemm(const float* __restrict__ W,
                                                 const float* __restrict__ Rm) {
    __shared__ float As[8][128];
    __shared__ float Bs[8][128];

    const float* A = (blockIdx.z == 0) ? W : Rm;
    const float* B = Rm;
    float* O = (blockIdx.z == 0) ? g_W2 : g_R2;

    const int tid = threadIdx.x;
    const int m0 = blockIdx.y * 128;
    const int n0 = blockIdx.x * 128;

    const int ar = tid >> 1;
    const int ac = (tid & 1) * 4;
    const int br = tid >> 5;
    const int bc = (tid & 31) * 4;
    const int tx = tid & 15;
    const int ty = tid >> 4;

    unsigned long long acc[8][4];
#pragma unroll
    for (int i = 0; i < 8; i++)
#pragma unroll
        for (int j = 0; j < 4; j++) acc[i][j] = 0ull;

    float4 xa = *reinterpret_cast<const float4*>(&A[(size_t)(m0 + ar) * ND + ac]);
    float4 wb = *reinterpret_cast<const float4*>(&B[(size_t)br * NU + n0 + bc]);

    const int KT = ND / 8;
    for (int kt = 0; kt < KT; kt++) {
        As[ac + 0][ar] = xa.x; As[ac + 1][ar] = xa.y;
        As[ac + 2][ar] = xa.z; As[ac + 3][ar] = xa.w;
        *reinterpret_cast<float4*>(&Bs[br][bc]) = wb;
        __syncthreads();
        if (kt + 1 < KT) {
            xa = *reinterpret_cast<const float4*>(&A[(size_t)(m0 + ar) * ND + (kt + 1) * 8 + ac]);
            wb = *reinterpret_cast<const float4*>(&B[(size_t)((kt + 1) * 8 + br) * NU + n0 + bc]);
        }
#pragma unroll
        for (int k = 0; k < 8; k++) {
            float4 a0 = *reinterpret_cast<const float4*>(&As[k][ty * 8]);
            float4 a1 = *reinterpret_cast<const float4*>(&As[k][ty * 8 + 4]);
            ulonglong2 bq0 = *reinterpret_cast<const ulonglong2*>(&Bs[k][tx * 8]);
            ulonglong2 bq1 = *reinterpret_cast<const ulonglong2*>(&Bs[k][tx * 8 + 4]);
            float av[8] = {a0.x, a0.y, a0.z, a0.w, a1.x, a1.y, a1.z, a1.w};
#pragma unroll
            for (int i = 0; i < 8; i++) {
                unsigned long long aa = pk2s(av[i]);
                fma2(acc[i][0], aa, bq0.x); fma2(acc[i][1], aa, bq0.y);
                fma2(acc[i][2], aa, bq1.x); fma2(acc[i][3], aa, bq1.y);
            }
        }
        __syncthreads();
    }
#pragma unroll
    for (int i = 0; i < 8; i++) {
        size_t row = (size_t)(m0 + ty * 8 + i);
        float2* op = reinterpret_cast<float2*>(&O[row * NU + n0 + tx * 8]);
        op[0] = upk2(acc[i][0]); op[1] = upk2(acc[i][1]);
        op[2] = upk2(acc[i][2]); op[3] = upk2(acc[i][3]);
    }
}

// ======================================================================
// Kernel A: A_cat = [x_t | x_{t-1}] (fp32) -> hi/lo bf16 (t=0: 2nd half 0)
// ======================================================================
__global__ __launch_bounds__(256) void conv_a(const float* __restrict__ X) {
    const size_t gidx = ((size_t)blockIdx.x * 256 + threadIdx.x) * 4;
    const int m = (int)(gidx >> 10);          // row 0..32767
    const int kk = (int)(gidx & 1023);        // 4-aligned

    float4 v;
    if (kk < ND) {
        v = *reinterpret_cast<const float4*>(&X[(size_t)m * ND + kk]);
    } else if ((m & (NT - 1)) == 0) {
        v = make_float4(0.f, 0.f, 0.f, 0.f);
    } else {
        v = *reinterpret_cast<const float4*>(&X[(size_t)(m - 1) * ND + (kk - ND)]);
    }
    float vv[4] = {v.x, v.y, v.z, v.w};
    __nv_bfloat16 hi[4], lo[4];
#pragma unroll
    for (int i = 0; i < 4; i++) {
        hi[i] = __float2bfloat16_rn(vv[i]);
        lo[i] = __float2bfloat16_rn(vv[i] - __bfloat162float(hi[i]));
    }
    __nv_bfloat162* dh = reinterpret_cast<__nv_bfloat162*>(&g_Ahi[gidx]);
    __nv_bfloat162* dl = reinterpret_cast<__nv_bfloat162*>(&g_Alo[gidx]);
    dh[0] = __nv_bfloat162(hi[0], hi[1]); dh[1] = __nv_bfloat162(hi[2], hi[3]);
    dl[0] = __nv_bfloat162(lo[0], lo[1]); dl[1] = __nv_bfloat162(lo[2], lo[3]);
}

// ======================================================================
// Kernel B: Wt[n][kk] = bf16 hi/lo of Wcat[kk][n],  Wcat = [W ; W2].
// ======================================================================
__global__ __launch_bounds__(256) void conv_w(const float* __restrict__ W) {
    const int kk = blockIdx.x;
#pragma unroll
    for (int h = 0; h < 2; h++) {
        const int n = threadIdx.x + h * 256;
        float v = (kk < ND) ? W[(size_t)kk * NU + n] : g_W2[(size_t)(kk - ND) * NU + n];
        __nv_bfloat16 hi = __float2bfloat16_rn(v);
        __nv_bfloat16 lo = __float2bfloat16_rn(v - __bfloat162float(hi));
        g_Wthi[(size_t)n * KCAT + kk] = hi;
        g_Wtlo[(size_t)n * KCAT + kk] = lo;
    }
}

// ======================================================================
// Kernel 1: z = A_cat @ Wcat via mma.sync bf16-split (base-ISA HMMA;
// tcgen05 is unavailable: harness compiles compute_103, not 103a).
//   z = Ahi@Bhi + Ahi@Blo + Alo@Bhi  (fp32 accumulators, 3 fused passes)
// Block 128x128, 8 warps (64x32 each), K-chunk 64 (SW128 atom row),
// cp.async 2-stage double buffer, conflict-free direct LDS fragments.
// ======================================================================
__device__ __forceinline__ void cpa16(uint32_t saddr, const void* gaddr) {
    asm volatile("cp.async.cg.shared.global [%0], [%1], 16;"
                 :: "r"(saddr), "l"(gaddr) : "memory");
}
__device__ __forceinline__ uint32_t lds32(uint32_t addr) {
    uint32_t v;
    asm volatile("ld.shared.b32 %0, [%1];" : "=r"(v) : "r"(addr));
    return v;
}
__device__ __forceinline__ void mma16816(float* d, uint32_t a0, uint32_t a1,
                                         uint32_t a2, uint32_t a3,
                                         uint32_t b0, uint32_t b1) {
    asm volatile(
        "mma.sync.aligned.m16n8k16.row.col.f32.bf16.bf16.f32 "
        "{%0,%1,%2,%3}, {%4,%5,%6,%7}, {%8,%9}, {%0,%1,%2,%3};"
        : "+f"(d[0]), "+f"(d[1]), "+f"(d[2]), "+f"(d[3])
        : "r"(a0), "r"(a1), "r"(a2), "r"(a3), "r"(b0), "r"(b1));
}

#define ZM_SMEM 65536   // 2 x (A 16KB + B 16KB)

__global__ __launch_bounds__(256) void zcat_mma() {
    extern __shared__ __align__(16) char smza[];
    const uint32_t sb = (uint32_t)__cvta_generic_to_shared(smza);
    const int tid = threadIdx.x;
    const int wid = tid >> 5;
    const int lane = tid & 31;
    const int m0 = blockIdx.y * 128;
    const int n0 = blockIdx.x * 128;
    const int wm = wid & 1;       // 0/1 -> 64-row half
    const int wn = wid >> 1;      // 0..3 -> 32-col strip

    float acc[4][4][4];
#pragma unroll
    for (int mf = 0; mf < 4; mf++)
#pragma unroll
        for (int nf = 0; nf < 4; nf++)
#pragma unroll
            for (int j = 0; j < 4; j++) acc[mf][nf][j] = 0.f;

    // loader role: row = tid/2, four 16B chunks at (tid&1)*4 + g
    const int lr = tid >> 1;
    const int lcg = (tid & 1) * 4;

    // issue tile `it` (0..47): pass p = it/16, chunk c = it%16
#define ZISSUE(it)                                                              \
    {                                                                           \
        const int p_ = (it) >> 4, c_ = (it) & 15;                               \
        const __nv_bfloat16* Ag = (p_ < 2) ? g_Ahi : g_Alo;                     \
        const __nv_bfloat16* Bg = (p_ == 1) ? g_Wtlo : g_Wthi;                  \
        const uint32_t ab = sb + ((it) & 1) * 32768;                            \
        const uint32_t bb = ab + 16384;                                         \
        const char* ga = (const char*)&Ag[(size_t)(m0 + lr) * KCAT + c_ * 64];  \
        const char* gb = (const char*)&Bg[(size_t)(n0 + lr) * KCAT + c_ * 64];  \
        _Pragma("unroll")                                                       \
        for (int g = 0; g < 4; g++) {                                           \
            uint32_t off = SWZ128((uint32_t)(lr * 128 + (lcg + g) * 16));       \
            cpa16(ab + off, ga + (size_t)(lcg + g) * 16);                       \
            cpa16(bb + off, gb + (size_t)(lcg + g) * 16);                       \
        }                                                                       \
        asm volatile("cp.async.commit_group;" ::: "memory");                    \
    }

    ZISSUE(0);
    for (int it = 0; it < 48; it++) {
        if (it + 1 < 48) {
            ZISSUE(it + 1);
            asm volatile("cp.async.wait_group 1;" ::: "memory");
        } else {
            asm volatile("cp.async.wait_group 0;" ::: "memory");
        }
        __syncthreads();

        const uint32_t ab = sb + (it & 1) * 32768;
        const uint32_t bb = ab + 16384;
#pragma unroll
        for (int ks = 0; ks < 4; ks++) {
            const int kbyte = ks * 32 + 4 * (lane & 3);   // 2*k0 + lane k-pair
            // B fragments (b0: k0..k0+7, b1: +8)
            uint32_t bf[4][2];
#pragma unroll
            for (int nf = 0; nf < 4; nf++) {
                const uint32_t base = (uint32_t)((wn * 32 + nf * 8 + (lane >> 2)) * 128 + kbyte);
                bf[nf][0] = lds32(bb + SWZ128(base));
                bf[nf][1] = lds32(bb + SWZ128(base + 16));
            }
#pragma unroll
            for (int mf = 0; mf < 4; mf++) {
                const uint32_t base = (uint32_t)((wm * 64 + mf * 16 + (lane >> 2)) * 128 + kbyte);
                const uint32_t a0 = lds32(ab + SWZ128(base));
                const uint32_t a1 = lds32(ab + SWZ128(base + 8 * 128));
                const uint32_t a2 = lds32(ab + SWZ128(base + 16));
                const uint32_t a3 = lds32(ab + SWZ128(base + 8 * 128 + 16));
#pragma unroll
                for (int nf = 0; nf < 4; nf++)
                    mma16816(acc[mf][nf], a0, a1, a2, a3, bf[nf][0], bf[nf][1]);
            }
        }
        __syncthreads();
    }

    // epilogue: d0,d1 -> (row, col..col+1); d2,d3 -> (row+8, ..)
#pragma unroll
    for (int mf = 0; mf < 4; mf++) {
        const int row = m0 + wm * 64 + mf * 16 + (lane >> 2);
#pragma unroll
        for (int nf = 0; nf < 4; nf++) {
            const int col = n0 + wn * 32 + nf * 8 + 2 * (lane & 3);
            *reinterpret_cast<float2*>(&g_z[(size_t)row * NU + col]) =
                make_float2(acc[mf][nf][0], acc[mf][nf][1]);
            *reinterpret_cast<float2*>(&g_z[(size_t)(row + 8) * NU + col]) =
                make_float2(acc[mf][nf][2], acc[mf][nf][3]);
        }
    }
}

// ======================================================================
// Kernel 2: lag-2 scan, batched rounds (EXACT R13 config — best known).
// ======================================================================
__global__ __launch_bounds__(256, 1) __cluster_dims__(8, 1, 1)
void scan_kernel(float* __restrict__ out) {
    __shared__ alignas(16) float hbuf[2][8][2][2][64];  // [par][srcRank][chain][batch][unit] 16KB
    __shared__ alignas(16) float red[2][16][2][16][4];  // [chain][kb][b][q][j]               16KB
    __shared__ alignas(8) unsigned long long mbar[2];   // [parity]

    const int tid = threadIdx.x;
    uint32_t rank;
    asm("mov.u32 %0, %%cluster_ctarank;" : "=r"(rank));
    const int cluster = blockIdx.x >> 3;
    const int b0 = cluster * 2;
    const int useg = (int)rank * 64;

    const int q = tid & 15;                   // u-quad (16 quads = 64 units)
    const int kb = tid >> 4;                  // k block (16 blocks of 32)
    const int ug = useg + q * 4;
    const int k0 = kb * 32;

    // R2 slice as k-pairs: Rp[j][i] = {R2[k0+2i][ug+j], R2[k0+2i+1][ug+j]}
    unsigned long long Rp[4][16];
#pragma unroll
    for (int i = 0; i < 16; i++) {
        float4 v0 = *reinterpret_cast<const float4*>(&g_R2[(size_t)(k0 + 2 * i) * NU + ug]);
        float4 v1 = *reinterpret_cast<const float4*>(&g_R2[(size_t)(k0 + 2 * i + 1) * NU + ug]);
        Rp[0][i] = pk2(v0.x, v1.x);
        Rp[1][i] = pk2(v0.y, v1.y);
        Rp[2][i] = pk2(v0.z, v1.z);
        Rp[3][i] = pk2(v0.w, v1.w);
    }

    // zero both h parities (round 0 reads parity 0 = zeros -> h = z)
    for (int i = tid; i < 2 * 8 * 2 * 2 * 64; i += 256) (&hbuf[0][0][0][0][0])[i] = 0.f;

    uint32_t barL[2];
#pragma unroll
    for (int p = 0; p < 2; p++)
        barL[p] = (uint32_t)__cvta_generic_to_shared(&mbar[p]);
    if (tid == 0) {
#pragma unroll
        for (int p = 0; p < 2; p++) {
            asm volatile("mbarrier.init.shared.b64 [%0], 1;" :: "r"(barL[p]) : "memory");
            asm volatile("mbarrier.arrive.expect_tx.shared.b64 _, [%0], %1;"
                         :: "r"(barL[p]), "r"(7168) : "memory");  // 7 x 1024B
        }
    }
    __syncthreads();
    // one-time rendezvous: inits/arms + zeroed hbuf visible before any bulk
    asm volatile("barrier.cluster.arrive.aligned;" ::: "memory");
    asm volatile("barrier.cluster.wait.aligned;" ::: "memory");

    // owner threads (tid<128): one (batch, unit) output each, both chains
    const bool owner = tid < 128;
    const int ob = tid >> 6;
    const int ou = tid & 63;
    const int oq = ou >> 2, oj = ou & 3;
    const float* zbase = &g_z[((size_t)(b0 + ob) * NT) * NU + useg + ou];
    float* obase = &out[((size_t)(b0 + ob) * NT) * NU + useg + ou];
    float zcur[2];
    zcur[0] = owner ? zbase[0] : 0.f;              // t = 0
    zcur[1] = owner ? zbase[(size_t)NU] : 0.f;     // t = 1

    // sender endpoint tables (tid 0..6, one dest CTA each), per write-parity
    uint32_t srcA[2], dstA[2], mbR[2];
    if (tid < 7) {
        const int d = (tid < (int)rank) ? tid : tid + 1;
#pragma unroll
        for (int wp = 0; wp < 2; wp++) {
            srcA[wp] = (uint32_t)__cvta_generic_to_shared(&hbuf[wp][rank][0][0][0]);
            asm("mapa.shared::cluster.u32 %0, %1, %2;"
                : "=r"(dstA[wp]) : "r"(srcA[wp]), "r"(d));
            asm("mapa.shared::cluster.u32 %0, %1, %2;"
                : "=r"(mbR[wp]) : "r"(barL[wp]), "r"(d));
        }
    }

    int par2[2] = {0, 0};

    for (int r = 0; r < NR; r++) {
        const int p = r & 1;          // read parity
        const int wp = p ^ 1;         // write parity (consumed at round r+1)

        if (r >= 1) {
            const uint32_t ba = barL[p];
            const uint32_t ph = (uint32_t)par2[p];
            uint32_t done;
            asm volatile(
                "{\n\t.reg .pred p;\n\t"
                "mbarrier.try_wait.parity.acquire.cta.shared::cta.b64 p, [%1], %2;\n\t"
                "selp.b32 %0, 1, 0, p;\n\t}"
                : "=r"(done) : "r"(ba), "r"(ph) : "memory");
            while (!done) {
                asm volatile(
                    "{\n\t.reg .pred p;\n\t"
                    "mbarrier.try_wait.parity.acquire.cta.shared::cta.b64 p, [%1], %2, 0x989680;\n\t"
                    "selp.b32 %0, 1, 0, p;\n\t}"
                    : "=r"(done) : "r"(ba), "r"(ph) : "memory");
            }
            par2[p] ^= 1;
            // re-arm for round r+2 (tid0's own sends at r follow in program
            // order -> peers' r+1 sends are gated by my r sends -> causal)
            if (tid == 0 && (r + 2) < NR) {
                asm volatile("mbarrier.arrive.expect_tx.shared.b64 _, [%0], %1;"
                             :: "r"(ba), "r"(7168) : "memory");
            }
        }
        // ONE barrier per round: orders owners' round-(r-1) LOCAL staging
        // stores before all warps' reads this round.
        __syncthreads();

        // prefetch z for round r+1 (consumed next round -> full round to land)
        float znxt[2] = {0.f, 0.f};
        if (owner && (r + 1) < NR) {
            znxt[0] = zbase[(size_t)(2 * (r + 1) + 0) * NU];
            znxt[1] = zbase[(size_t)(2 * (r + 1) + 1) * NU];
        }

        // ---- matvec both chains, accumulators reused ----
#pragma unroll
        for (int c = 0; c < 2; c++) {
            const float* h0 = &hbuf[p][kb >> 1][c][0][(kb & 1) * 32];
            const float* h1 = &hbuf[p][kb >> 1][c][1][(kb & 1) * 32];
            unsigned long long acc[2][4][2];
#pragma unroll
            for (int b = 0; b < 2; b++)
#pragma unroll
                for (int j = 0; j < 4; j++) { acc[b][j][0] = 0ull; acc[b][j][1] = 0ull; }

#pragma unroll
            for (int g = 0; g < 8; g++) {
                ulonglong2 hp0 = *reinterpret_cast<const ulonglong2*>(&h0[g * 4]);
                ulonglong2 hp1 = *reinterpret_cast<const ulonglong2*>(&h1[g * 4]);
#pragma unroll
                for (int j = 0; j < 4; j++) {
                    fma2(acc[0][j][0], Rp[j][2 * g + 0], hp0.x);
                    fma2(acc[0][j][1], Rp[j][2 * g + 1], hp0.y);
                    fma2(acc[1][j][0], Rp[j][2 * g + 0], hp1.x);
                    fma2(acc[1][j][1], Rp[j][2 * g + 1], hp1.y);
                }
            }
            // stash partials: one STS.128 per batch
#pragma unroll
            for (int b = 0; b < 2; b++) {
                float pj[4];
#pragma unroll
                for (int j = 0; j < 4; j++) {
                    float2 s0 = upk2(acc[b][j][0]);
                    float2 s1 = upk2(acc[b][j][1]);
                    pj[j] = (s0.x + s0.y) + (s1.x + s1.y);
                }
                *reinterpret_cast<float4*>(&red[c][kb][b][q][0]) =
                    make_float4(pj[0], pj[1], pj[2], pj[3]);
            }
        }
        __syncthreads();   // all partials staged (all 256 threads)

        if (owner) {
            float val[2];
#pragma unroll
            for (int c = 0; c < 2; c++) {
                float s = 0.f;
#pragma unroll
                for (int r8 = 0; r8 < 16; r8++) s += red[c][r8][ob][oq][oj];
                val[c] = zcur[c] + s;
                obase[(size_t)(2 * r + c) * NU] = val[c];
            }
            if (r + 1 < NR) {
                hbuf[wp][rank][0][ob][ou] = val[0];   // local staging (own slice)
                hbuf[wp][rank][1][ob][ou] = val[1];
                asm volatile("bar.sync 1, 128;" ::: "memory");  // slice complete
                if (tid < 7) {
                    asm volatile("fence.proxy.async.shared::cta;" ::: "memory");
                    asm volatile(
                        "cp.async.bulk.shared::cluster.shared::cta.mbarrier::complete_tx::bytes "
                        "[%0], [%1], %2, [%3];"
                        :: "r"(dstA[wp]), "r"(srcA[wp]), "r"(1024), "r"(mbR[wp])
                        : "memory");
                }
            }
        }
        zcur[0] = znxt[0];
        zcur[1] = znxt[1];
    }

    // final rendezvous: no CTA exits while peers could still touch its smem
    asm volatile("barrier.cluster.arrive.aligned;" ::: "memory");
    asm volatile("barrier.cluster.wait.aligned;" ::: "memory");
}

// ======================================================================
extern "C" void kernel_launch(void* const* d_in, const int* in_sizes, int n_in,
                              void* d_out, int out_size) {
    const float* x = (const float*)d_in[0];            // [32,1024,512]
    const float* W = (const float*)d_in[1];            // kernel [512,512]
    const float* R = (const float*)d_in[2];            // recurrent_kernel [512,512]
    float* out = (float*)d_out;                        // [32,1024,512]

    cudaFuncSetAttribute(zcat_mma, cudaFuncAttributeMaxDynamicSharedMemorySize, ZM_SMEM);

    prep_gemm<<<dim3(4, 4, 2), 256>>>(W, R);           // W2 = W@R, R2 = R@R
    conv_a<<<32768, 256>>>(x);                         // x -> Ahi/Alo (with shift)
    conv_w<<<1024, 256>>>(W);                          // [W;W2]^T -> Wthi/Wtlo
    zcat_mma<<<dim3(4, 256), 256, ZM_SMEM>>>();        // mma.sync bf16-split z GEMM
    scan_kernel<<<128, 256>>>(out);                    // R13 lag-2 scan (best known)
}